// round 12
// baseline (speedup 1.0000x reference)
#include <cuda_runtime.h>
#include <cuda_fp16.h>
#include <cstdint>

#define NNODES 50000
#define NEDGES 800000
#define NEPAD (NEDGES + 4 * NNODES)   // CSR capacity with per-node pad-to-4
#define NF 128
#define NGRAPH 512
#define NCLS 10
#define SCAN_BLOCKS ((NNODES + 1023) / 1024)   // 49

#define ASTRIDE 136                        // halves per smem row (272 B, 16B-aligned)
#define GEMM_SMEM (2 * 128 * ASTRIDE * 2)  // 69632 B

// ---------------- device scratch (static: no allocations allowed) ----------
__device__ __half g_h[NNODES * NF];     // activations (fp16); layer0 = fp16(x)
__device__ __half g_hw[NNODES * NF];    // h @ W[l]  (fp16)
__device__ __half g_wh[3 * NF * NF];    // fp16 weights
__device__ float  g_dinv[NNODES];
__device__ int    g_deg[NNODES];
__device__ int    g_off[NNODES + 1];    // padded CSR offsets (multiples of 4)
__device__ int    g_cur[NNODES];
__device__ __align__(16) int   g_row[NEPAD];    // zero-init: padding rows stay 0
__device__ __align__(16) float g_enorm[NEPAD];  // zero-init: padding norms stay 0
__device__ float  g_pool[NGRAPH * NF];
__device__ int    g_bsum[SCAN_BLOCKS];
__device__ int    g_boff[SCAN_BLOCKS];

// ---------------- init ----------
__global__ void k_zero() {
    int i = blockIdx.x * blockDim.x + threadIdx.x;
    if (i < NGRAPH * NF) g_pool[i] = 0.0f;
    if (i < NNODES) g_deg[i] = 0;
}

// convert x -> g_h (fp16) and W -> g_wh (fp16), one shot
__global__ void k_cvt(const float* __restrict__ x, const float* __restrict__ W) {
    int i = blockIdx.x * blockDim.x + threadIdx.x;   // float4 index
    if (i < NNODES * NF / 4) {
        float4 v = *(const float4*)(x + (size_t)i * 4);
        __half2 h0 = __floats2half2_rn(v.x, v.y);
        __half2 h1 = __floats2half2_rn(v.z, v.w);
        *(uint2*)(g_h + (size_t)i * 4) =
            make_uint2(*(uint32_t*)&h0, *(uint32_t*)&h1);
    }
    if (i < 3 * NF * NF / 4) {
        float4 v = *(const float4*)(W + (size_t)i * 4);
        __half2 h0 = __floats2half2_rn(v.x, v.y);
        __half2 h1 = __floats2half2_rn(v.z, v.w);
        *(uint2*)(g_wh + (size_t)i * 4) =
            make_uint2(*(uint32_t*)&h0, *(uint32_t*)&h1);
    }
}

__global__ void k_count(const int* __restrict__ col) {
    int e = blockIdx.x * blockDim.x + threadIdx.x;
    if (e < NEDGES) {
        int c = col[e];
        c = min(max(c, 0), NNODES - 1);
        atomicAdd(&g_deg[c], 1);
    }
}

// ---------- scan stage A over padded degrees (+ dinv fused) ----------
__global__ __launch_bounds__(1024) void k_scan_a() {
    int i = blockIdx.x * 1024 + threadIdx.x;
    int lane = threadIdx.x & 31;
    int wid = threadIdx.x >> 5;
    int deg = (i < NNODES) ? g_deg[i] : 0;
    if (i < NNODES) g_dinv[i] = rsqrtf((float)(deg + 1));  // +1 self-loop
    int v = (deg + 3) & ~3;   // pad each node's segment to multiple of 4

    int incl = v;
#pragma unroll
    for (int d = 1; d < 32; d <<= 1) {
        int t = __shfl_up_sync(0xffffffffu, incl, d);
        if (lane >= d) incl += t;
    }
    __shared__ int wsum[32];
    if (lane == 31) wsum[wid] = incl;
    __syncthreads();
    if (wid == 0) {
        int s = wsum[lane];
#pragma unroll
        for (int d = 1; d < 32; d <<= 1) {
            int t = __shfl_up_sync(0xffffffffu, s, d);
            if (lane >= d) s += t;
        }
        wsum[lane] = s;
    }
    __syncthreads();
    int warpoff = (wid > 0) ? wsum[wid - 1] : 0;
    int excl = warpoff + incl - v;
    if (i < NNODES) g_off[i] = excl;
    if (threadIdx.x == 1023) g_bsum[blockIdx.x] = warpoff + incl;
}

__global__ void k_scan_b() {
    __shared__ int s[64];
    int tid = threadIdx.x;
    int v = (tid < SCAN_BLOCKS) ? g_bsum[tid] : 0;
    s[tid] = v;
    __syncthreads();
#pragma unroll
    for (int d = 1; d < 64; d <<= 1) {
        int t = (tid >= d) ? s[tid - d] : 0;
        __syncthreads();
        s[tid] += t;
        __syncthreads();
    }
    if (tid < SCAN_BLOCKS) g_boff[tid] = s[tid] - v;
    if (tid == SCAN_BLOCKS - 1) g_off[NNODES] = s[tid];  // padded total
}

__global__ __launch_bounds__(1024) void k_scan_c() {
    int i = blockIdx.x * 1024 + threadIdx.x;
    if (i < NNODES) {
        int o = g_off[i] + g_boff[blockIdx.x];
        g_off[i] = o;
        g_cur[i] = o;
    }
}

__global__ void k_fill(const int* __restrict__ rowp,
                       const int* __restrict__ colp) {
    int e = blockIdx.x * blockDim.x + threadIdx.x;
    if (e < NEDGES) {
        int c = colp[e];
        c = min(max(c, 0), NNODES - 1);
        int r = rowp[e];
        r = min(max(r, 0), NNODES - 1);
        int p = atomicAdd(&g_cur[c], 1);
        if (p >= 0 && p < NEPAD) {
            g_row[p] = r;
            g_enorm[p] = g_dinv[r] * g_dinv[c];
        }
    }
}

// ---------------- mma / ldmatrix / cp.async helpers ----------------
__device__ __forceinline__ void mma_f16(float* c, const uint32_t* a,
                                        uint32_t b0, uint32_t b1) {
    asm volatile(
        "mma.sync.aligned.m16n8k16.row.col.f32.f16.f16.f32 "
        "{%0,%1,%2,%3}, {%4,%5,%6,%7}, {%8,%9}, {%0,%1,%2,%3};"
        : "+f"(c[0]), "+f"(c[1]), "+f"(c[2]), "+f"(c[3])
        : "r"(a[0]), "r"(a[1]), "r"(a[2]), "r"(a[3]), "r"(b0), "r"(b1));
}
__device__ __forceinline__ uint32_t smem_u32(const void* p) {
    return (uint32_t)__cvta_generic_to_shared(p);
}
__device__ __forceinline__ void ldsm_x4(uint32_t& r0, uint32_t& r1,
                                        uint32_t& r2, uint32_t& r3, uint32_t a) {
    asm volatile("ldmatrix.sync.aligned.m8n8.x4.shared.b16 {%0,%1,%2,%3}, [%4];"
                 : "=r"(r0), "=r"(r1), "=r"(r2), "=r"(r3) : "r"(a));
}
__device__ __forceinline__ void ldsm_x4_t(uint32_t& r0, uint32_t& r1,
                                          uint32_t& r2, uint32_t& r3, uint32_t a) {
    asm volatile("ldmatrix.sync.aligned.m8n8.x4.trans.shared.b16 {%0,%1,%2,%3}, [%4];"
                 : "=r"(r0), "=r"(r1), "=r"(r2), "=r"(r3) : "r"(a));
}
__device__ __forceinline__ void cp16(uint32_t dst, const void* src, bool pred) {
    asm volatile(
        "{\n\t.reg .pred p;\n\tsetp.ne.u32 p, %2, 0;\n\t"
        "@p cp.async.cg.shared.global [%0], [%1], 16;\n\t}"
        :: "r"(dst), "l"(src), "r"((int)pred));
}

// -------- GEMM (fp16 m16n8k16, full-K tiles, cp.async + ldmatrix) ----------
// A = g_h (fp16 always), W = g_wh (fp16). Out fp16 g_hw.
__global__ __launch_bounds__(256, 2) void k_gemm(int layer) {
    extern __shared__ __half sm[];
    __half (*As)[ASTRIDE] = (__half(*)[ASTRIDE])sm;                   // [m][k]
    __half (*Wk)[ASTRIDE] = (__half(*)[ASTRIDE])(sm + 128 * ASTRIDE); // [k][n]

    int bm = blockIdx.x * 128;
    int tid = threadIdx.x;
    int warp = tid >> 5, lane = tid & 31;
    int wr = warp >> 1;        // m slab (32 rows)
    int wc = warp & 1;         // n slab (64 cols)
    int g = lane >> 2;
    int tig = lane & 3;
    int lm = lane >> 3;        // ldmatrix matrix id 0..3
    int lr = lane & 7;         // ldmatrix row-in-matrix

    // ---- stage both tiles via cp.async: thread -> (row, 128B-half) ----
    {
        int row = tid >> 1;          // 0..127
        int hsel = (tid & 1) * 64;   // half-row offset in halves (128 B)
        bool av = (bm + row) < NNODES;
        const __half* asrc = g_h + (size_t)(bm + row) * NF + hsel;
        uint32_t adst = smem_u32(&As[row][hsel]);
#pragma unroll
        for (int c = 0; c < 8; c++) cp16(adst + c * 16, asrc + c * 8, av);
        const __half* wsrc = g_wh + (size_t)layer * NF * NF + (size_t)row * NF + hsel;
        uint32_t wdst = smem_u32(&Wk[row][hsel]);
#pragma unroll
        for (int c = 0; c < 8; c++) cp16(wdst + c * 16, wsrc + c * 8, true);
    }
    asm volatile("cp.async.commit_group;");
    asm volatile("cp.async.wait_group 0;" ::: "memory");
    __syncthreads();

    float acc[2][8][4];
#pragma unroll
    for (int ti = 0; ti < 2; ti++)
#pragma unroll
        for (int tj = 0; tj < 8; tj++)
#pragma unroll
            for (int q = 0; q < 4; q++) acc[ti][tj][q] = 0.0f;

    // per-lane ldmatrix sub-offsets
    int a_roff = (lm & 1) * 8 + lr;      // A: row offset within 16-row tile
    int a_koff = (lm >> 1) * 8;          // A: k offset within 16-k slice
    int b_koff = (lm & 1) * 8 + lr;      // B: k row within 16-k slice
    int b_noff = (lm >> 1) * 8;          // B: n offset within 16-n pair

#pragma unroll
    for (int kk = 0; kk < NF; kk += 16) {
        uint32_t a[2][4];
        ldsm_x4(a[0][0], a[0][1], a[0][2], a[0][3],
                smem_u32(&As[wr * 32 + a_roff][kk + a_koff]));
        ldsm_x4(a[1][0], a[1][1], a[1][2], a[1][3],
                smem_u32(&As[wr * 32 + 16 + a_roff][kk + a_koff]));
        uint32_t bf[4][4];
#pragma unroll
        for (int tjp = 0; tjp < 4; tjp++)
            ldsm_x4_t(bf[tjp][0], bf[tjp][1], bf[tjp][2], bf[tjp][3],
                      smem_u32(&Wk[kk + b_koff][wc * 64 + tjp * 16 + b_noff]));
#pragma unroll
        for (int tj = 0; tj < 8; tj++) {
            uint32_t b0 = bf[tj >> 1][(tj & 1) * 2 + 0];
            uint32_t b1 = bf[tj >> 1][(tj & 1) * 2 + 1];
            mma_f16(acc[0][tj], a[0], b0, b1);
            mma_f16(acc[1][tj], a[1], b0, b1);
        }
    }

#pragma unroll
    for (int ti = 0; ti < 2; ti++) {
#pragma unroll
        for (int tj = 0; tj < 8; tj++) {
            int row = bm + wr * 32 + ti * 16 + g;
            int col = wc * 64 + tj * 8 + tig * 2;
            if (row < NNODES)
                *(__half2*)(g_hw + (size_t)row * NF + col) =
                    __floats2half2_rn(acc[ti][tj][0], acc[ti][tj][1]);
            if (row + 8 < NNODES)
                *(__half2*)(g_hw + (size_t)(row + 8) * NF + col) =
                    __floats2half2_rn(acc[ti][tj][2], acc[ti][tj][3]);
        }
    }
}

// ------- gather (8-wide unroll) + self-loop + bias + relu ------------------
template <bool DO_POOL>
__global__ __launch_bounds__(256) void k_gather(const float* __restrict__ ball,
                                                int layer,
                                                const int* __restrict__ batch) {
    int node = blockIdx.x * 8 + (threadIdx.x >> 5);
    if (node >= NNODES) return;
    int lane = threadIdx.x & 31;

    const __half* __restrict__ hw = g_hw;
    const float* __restrict__ bias = ball + layer * NF;

    float4 acc = make_float4(0.f, 0.f, 0.f, 0.f);
    int s = g_off[node];
    int e = g_off[node + 1];   // s, e multiples of 4; padding has enorm==0
    int p = s;
    for (; p + 8 <= e; p += 8) {
        int4 rr0 = *(const int4*)(g_row + p);
        int4 rr1 = *(const int4*)(g_row + p + 4);
        float4 nm0 = *(const float4*)(g_enorm + p);
        float4 nm1 = *(const float4*)(g_enorm + p + 4);
        uint2 w0 = *(const uint2*)(hw + (size_t)rr0.x * NF + lane * 4);
        uint2 w1 = *(const uint2*)(hw + (size_t)rr0.y * NF + lane * 4);
        uint2 w2 = *(const uint2*)(hw + (size_t)rr0.z * NF + lane * 4);
        uint2 w3 = *(const uint2*)(hw + (size_t)rr0.w * NF + lane * 4);
        uint2 w4 = *(const uint2*)(hw + (size_t)rr1.x * NF + lane * 4);
        uint2 w5 = *(const uint2*)(hw + (size_t)rr1.y * NF + lane * 4);
        uint2 w6 = *(const uint2*)(hw + (size_t)rr1.z * NF + lane * 4);
        uint2 w7 = *(const uint2*)(hw + (size_t)rr1.w * NF + lane * 4);
        float2 a0 = __half22float2(*(__half2*)&w0.x), a1 = __half22float2(*(__half2*)&w0.y);
        float2 b0 = __half22float2(*(__half2*)&w1.x), b1 = __half22float2(*(__half2*)&w1.y);
        float2 c0 = __half22float2(*(__half2*)&w2.x), c1 = __half22float2(*(__half2*)&w2.y);
        float2 d0 = __half22float2(*(__half2*)&w3.x), d1 = __half22float2(*(__half2*)&w3.y);
        float2 e0 = __half22float2(*(__half2*)&w4.x), e1 = __half22float2(*(__half2*)&w4.y);
        float2 f0 = __half22float2(*(__half2*)&w5.x), f1 = __half22float2(*(__half2*)&w5.y);
        float2 g0 = __half22float2(*(__half2*)&w6.x), g1 = __half22float2(*(__half2*)&w6.y);
        float2 h0 = __half22float2(*(__half2*)&w7.x), h1 = __half22float2(*(__half2*)&w7.y);
        acc.x += a0.x * nm0.x + b0.x * nm0.y + c0.x * nm0.z + d0.x * nm0.w
               + e0.x * nm1.x + f0.x * nm1.y + g0.x * nm1.z + h0.x * nm1.w;
        acc.y += a0.y * nm0.x + b0.y * nm0.y + c0.y * nm0.z + d0.y * nm0.w
               + e0.y * nm1.x + f0.y * nm1.y + g0.y * nm1.z + h0.y * nm1.w;
        acc.z += a1.x * nm0.x + b1.x * nm0.y + c1.x * nm0.z + d1.x * nm0.w
               + e1.x * nm1.x + f1.x * nm1.y + g1.x * nm1.z + h1.x * nm1.w;
        acc.w += a1.y * nm0.x + b1.y * nm0.y + c1.y * nm0.z + d1.y * nm0.w
               + e1.y * nm1.x + f1.y * nm1.y + g1.y * nm1.z + h1.y * nm1.w;
    }
    if (p < e) {   // one remaining 4-group
        int4 rr = *(const int4*)(g_row + p);
        float4 nm = *(const float4*)(g_enorm + p);
        uint2 w0 = *(const uint2*)(hw + (size_t)rr.x * NF + lane * 4);
        uint2 w1 = *(const uint2*)(hw + (size_t)rr.y * NF + lane * 4);
        uint2 w2 = *(const uint2*)(hw + (size_t)rr.z * NF + lane * 4);
        uint2 w3 = *(const uint2*)(hw + (size_t)rr.w * NF + lane * 4);
        float2 a0 = __half22float2(*(__half2*)&w0.x), a1 = __half22float2(*(__half2*)&w0.y);
        float2 b0 = __half22float2(*(__half2*)&w1.x), b1 = __half22float2(*(__half2*)&w1.y);
        float2 c0 = __half22float2(*(__half2*)&w2.x), c1 = __half22float2(*(__half2*)&w2.y);
        float2 d0 = __half22float2(*(__half2*)&w3.x), d1 = __half22float2(*(__half2*)&w3.y);
        acc.x += a0.x * nm.x + b0.x * nm.y + c0.x * nm.z + d0.x * nm.w;
        acc.y += a0.y * nm.x + b0.y * nm.y + c0.y * nm.z + d0.y * nm.w;
        acc.z += a1.x * nm.x + b1.x * nm.y + c1.x * nm.z + d1.x * nm.w;
        acc.w += a1.y * nm.x + b1.y * nm.y + c1.y * nm.z + d1.y * nm.w;
    }
    // self-loop
    {
        float di = g_dinv[node];
        float nm = di * di;
        uint2 w0 = *(const uint2*)(hw + (size_t)node * NF + lane * 4);
        float2 a0 = __half22float2(*(__half2*)&w0.x), a1 = __half22float2(*(__half2*)&w0.y);
        acc.x += a0.x * nm;
        acc.y += a0.y * nm;
        acc.z += a1.x * nm;
        acc.w += a1.y * nm;
    }
    float4 bb = *(const float4*)(bias + lane * 4);
    acc.x = fmaxf(acc.x + bb.x, 0.f);
    acc.y = fmaxf(acc.y + bb.y, 0.f);
    acc.z = fmaxf(acc.z + bb.z, 0.f);
    acc.w = fmaxf(acc.w + bb.w, 0.f);

    if (DO_POOL) {
        int gph = batch[node];
        gph = min(max(gph, 0), NGRAPH - 1);
        float* dst = g_pool + (size_t)gph * NF + lane * 4;
        atomicAdd(dst + 0, acc.x);
        atomicAdd(dst + 1, acc.y);
        atomicAdd(dst + 2, acc.z);
        atomicAdd(dst + 3, acc.w);
    } else {
        __half2 h01 = __floats2half2_rn(acc.x, acc.y);
        __half2 h23 = __floats2half2_rn(acc.z, acc.w);
        uint2 packed = make_uint2(*(uint32_t*)&h01, *(uint32_t*)&h23);
        *(uint2*)(g_h + (size_t)node * NF + lane * 4) = packed;
    }
}

// ---------------- output head ------------------
__global__ __launch_bounds__(128) void k_out(const float* __restrict__ Wout,
                                             const float* __restrict__ bout,
                                             float* __restrict__ out) {
    int w = blockIdx.x * 4 + (threadIdx.x >> 5);
    if (w >= NGRAPH) return;
    int lane = threadIdx.x & 31;
    float4 p = *(const float4*)(g_pool + (size_t)w * NF + lane * 4);
#pragma unroll
    for (int c = 0; c < NCLS; c++) {
        float sum = p.x * Wout[(lane * 4 + 0) * NCLS + c]
                  + p.y * Wout[(lane * 4 + 1) * NCLS + c]
                  + p.z * Wout[(lane * 4 + 2) * NCLS + c]
                  + p.w * Wout[(lane * 4 + 3) * NCLS + c];
#pragma unroll
        for (int o = 16; o > 0; o >>= 1)
            sum += __shfl_down_sync(0xffffffffu, sum, o);
        if (lane == 0) out[w * NCLS + c] = sum + bout[c];
    }
}

// ---------------- launch ----------
extern "C" void kernel_launch(void* const* d_in, const int* in_sizes, int n_in,
                              void* d_out, int out_size) {
    const float* x     = nullptr;
    const int*   ei    = nullptr;
    const int*   batch = nullptr;
    const float* W     = nullptr;
    const float* b     = nullptr;
    const float* Wout  = nullptr;
    const float* bout  = nullptr;
    for (int i = 0; i < n_in; i++) {
        switch (in_sizes[i]) {
            case NNODES * NF:      x     = (const float*)d_in[i]; break;
            case 2 * NEDGES:       ei    = (const int*)d_in[i];   break;
            case NNODES:           batch = (const int*)d_in[i];   break;
            case 3 * NF * NF:      W     = (const float*)d_in[i]; break;
            case 3 * NF:           b     = (const float*)d_in[i]; break;
            case NF * NCLS:        Wout  = (const float*)d_in[i]; break;
            case NCLS:             bout  = (const float*)d_in[i]; break;
            default: break;
        }
    }
    float* out = (float*)d_out;

    const int* rowp = ei;           // source nodes j
    const int* colp = ei + NEDGES;  // target nodes i

    cudaFuncSetAttribute(k_gemm, cudaFuncAttributeMaxDynamicSharedMemorySize,
                         GEMM_SMEM);

    k_zero<<<(NGRAPH * NF + 255) / 256, 256>>>();
    k_cvt<<<(NNODES * NF / 4 + 255) / 256, 256>>>(x, W);
    k_count<<<(NEDGES + 255) / 256, 256>>>(colp);
    // layer-0 GEMM (needs only g_h/g_wh) — launch #4 = profiler capture slot.
    k_gemm<<<(NNODES + 127) / 128, 256, GEMM_SMEM>>>(0);
    k_scan_a<<<SCAN_BLOCKS, 1024>>>();
    k_scan_b<<<1, 64>>>();
    k_scan_c<<<SCAN_BLOCKS, 1024>>>();
    k_fill<<<(NEDGES + 255) / 256, 256>>>(rowp, colp);

    k_gather<false><<<(NNODES + 7) / 8, 256>>>(b, 0, batch);
    k_gemm<<<(NNODES + 127) / 128, 256, GEMM_SMEM>>>(1);
    k_gather<false><<<(NNODES + 7) / 8, 256>>>(b, 1, batch);
    k_gemm<<<(NNODES + 127) / 128, 256, GEMM_SMEM>>>(2);
    k_gather<true><<<(NNODES + 7) / 8, 256>>>(b, 2, batch);

    k_out<<<NGRAPH / 4, 128>>>(Wout, bout, out);
}

// round 13
// speedup vs baseline: 1.0961x; 1.0961x over previous
#include <cuda_runtime.h>
#include <cuda_fp16.h>
#include <cstdint>

#define NNODES 50000
#define NEDGES 800000
#define NEPAD (NEDGES + 4 * NNODES)   // CSR capacity with per-node pad-to-4
#define NF 128
#define NGRAPH 512
#define NCLS 10
#define SCAN_BLOCKS ((NNODES + 1023) / 1024)   // 49

#define ASTRIDE 136                        // halves per smem row (272 B, 16B-aligned)
#define BM 64                              // GEMM M tile
#define GEMM_SMEM ((BM + 128) * ASTRIDE * 2)  // 52224 B

// ---------------- device scratch (static: no allocations allowed) ----------
__device__ __half g_h[NNODES * NF];     // layer activations (fp16)
__device__ __half g_hw[NNODES * NF];    // h @ W[l]  (fp16)
__device__ float  g_dinv[NNODES];
__device__ int    g_deg[NNODES];
__device__ int    g_off[NNODES + 1];    // padded CSR offsets (multiples of 4)
__device__ int    g_cur[NNODES];
__device__ __align__(16) int   g_row[NEPAD];    // zero-init: padding rows stay 0
__device__ __align__(16) float g_enorm[NEPAD];  // zero-init: padding norms stay 0
__device__ float  g_pool[NGRAPH * NF];
__device__ int    g_bsum[SCAN_BLOCKS];
__device__ int    g_boff[SCAN_BLOCKS];

// ---------------- init ----------
__global__ void k_zero() {
    int i = blockIdx.x * blockDim.x + threadIdx.x;
    if (i < NGRAPH * NF) g_pool[i] = 0.0f;
    if (i < NNODES) g_deg[i] = 0;
}

__global__ void k_count(const int* __restrict__ col) {
    int e = blockIdx.x * blockDim.x + threadIdx.x;
    if (e < NEDGES) {
        int c = col[e];
        c = min(max(c, 0), NNODES - 1);
        atomicAdd(&g_deg[c], 1);
    }
}

// ---------- scan stage A over padded degrees (+ dinv fused) ----------
__global__ __launch_bounds__(1024) void k_scan_a() {
    int i = blockIdx.x * 1024 + threadIdx.x;
    int lane = threadIdx.x & 31;
    int wid = threadIdx.x >> 5;
    int deg = (i < NNODES) ? g_deg[i] : 0;
    if (i < NNODES) g_dinv[i] = rsqrtf((float)(deg + 1));  // +1 self-loop
    int v = (deg + 3) & ~3;   // pad each node's segment to multiple of 4

    int incl = v;
#pragma unroll
    for (int d = 1; d < 32; d <<= 1) {
        int t = __shfl_up_sync(0xffffffffu, incl, d);
        if (lane >= d) incl += t;
    }
    __shared__ int wsum[32];
    if (lane == 31) wsum[wid] = incl;
    __syncthreads();
    if (wid == 0) {
        int s = wsum[lane];
#pragma unroll
        for (int d = 1; d < 32; d <<= 1) {
            int t = __shfl_up_sync(0xffffffffu, s, d);
            if (lane >= d) s += t;
        }
        wsum[lane] = s;
    }
    __syncthreads();
    int warpoff = (wid > 0) ? wsum[wid - 1] : 0;
    int excl = warpoff + incl - v;
    if (i < NNODES) g_off[i] = excl;
    if (threadIdx.x == 1023) g_bsum[blockIdx.x] = warpoff + incl;
}

__global__ void k_scan_b() {
    __shared__ int s[64];
    int tid = threadIdx.x;
    int v = (tid < SCAN_BLOCKS) ? g_bsum[tid] : 0;
    s[tid] = v;
    __syncthreads();
#pragma unroll
    for (int d = 1; d < 64; d <<= 1) {
        int t = (tid >= d) ? s[tid - d] : 0;
        __syncthreads();
        s[tid] += t;
        __syncthreads();
    }
    if (tid < SCAN_BLOCKS) g_boff[tid] = s[tid] - v;
    if (tid == SCAN_BLOCKS - 1) g_off[NNODES] = s[tid];  // padded total
}

__global__ __launch_bounds__(1024) void k_scan_c() {
    int i = blockIdx.x * 1024 + threadIdx.x;
    if (i < NNODES) {
        int o = g_off[i] + g_boff[blockIdx.x];
        g_off[i] = o;
        g_cur[i] = o;
    }
}

__global__ void k_fill(const int* __restrict__ rowp,
                       const int* __restrict__ colp) {
    int e = blockIdx.x * blockDim.x + threadIdx.x;
    if (e < NEDGES) {
        int c = colp[e];
        c = min(max(c, 0), NNODES - 1);
        int r = rowp[e];
        r = min(max(r, 0), NNODES - 1);
        int p = atomicAdd(&g_cur[c], 1);
        if (p >= 0 && p < NEPAD) {
            g_row[p] = r;
            g_enorm[p] = g_dinv[r] * g_dinv[c];
        }
    }
}

// ---------------- mma / ldmatrix helpers ----------------
__device__ __forceinline__ void mma_f16(float* c, const uint32_t* a,
                                        uint32_t b0, uint32_t b1) {
    asm volatile(
        "mma.sync.aligned.m16n8k16.row.col.f32.f16.f16.f32 "
        "{%0,%1,%2,%3}, {%4,%5,%6,%7}, {%8,%9}, {%0,%1,%2,%3};"
        : "+f"(c[0]), "+f"(c[1]), "+f"(c[2]), "+f"(c[3])
        : "r"(a[0]), "r"(a[1]), "r"(a[2]), "r"(a[3]), "r"(b0), "r"(b1));
}
__device__ __forceinline__ uint32_t smem_u32(const void* p) {
    return (uint32_t)__cvta_generic_to_shared(p);
}
__device__ __forceinline__ void ldsm_x4(uint32_t& r0, uint32_t& r1,
                                        uint32_t& r2, uint32_t& r3, uint32_t a) {
    asm volatile("ldmatrix.sync.aligned.m8n8.x4.shared.b16 {%0,%1,%2,%3}, [%4];"
                 : "=r"(r0), "=r"(r1), "=r"(r2), "=r"(r3) : "r"(a));
}
__device__ __forceinline__ void ldsm_x4_t(uint32_t& r0, uint32_t& r1,
                                          uint32_t& r2, uint32_t& r3, uint32_t a) {
    asm volatile("ldmatrix.sync.aligned.m8n8.x4.trans.shared.b16 {%0,%1,%2,%3}, [%4];"
                 : "=r"(r0), "=r"(r1), "=r"(r2), "=r"(r3) : "r"(a));
}

// -------- GEMM (fp16 m16n8k16, 64x128 tiles, ldmatrix fragments) -----------
// A = x (fp32, layer 0) or g_h (fp16). W staged [k][n] fp16; B frags via trans.
__global__ __launch_bounds__(256, 3) void k_gemm(const float* __restrict__ x,
                                                 const float* __restrict__ Wall,
                                                 int layer) {
    extern __shared__ __half sm[];
    __half (*As)[ASTRIDE] = (__half(*)[ASTRIDE])sm;                  // [m][k]
    __half (*Wk)[ASTRIDE] = (__half(*)[ASTRIDE])(sm + BM * ASTRIDE); // [k][n]

    const float* __restrict__ B = Wall + (size_t)layer * NF * NF;

    int bm = blockIdx.x * BM;
    int tid = threadIdx.x;
    int warp = tid >> 5, lane = tid & 31;
    int wr = warp >> 1;        // m slab (16 rows), 0..3
    int wc = warp & 1;         // n slab (64 cols)
    int g = lane >> 2;
    int tig = lane & 3;
    int lm = lane >> 3;        // ldmatrix matrix id 0..3
    int lr = lane & 7;         // ldmatrix row-in-matrix

    // ---- stage A tile (64 x 128 halves), one shot ----
    if (layer == 0) {
#pragma unroll
        for (int i = 0; i < 8; i++) {
            int e = tid + i * 256;
            int row = e >> 5;            // 32 float4 per row
            int kq = (e & 31) * 4;
            float4 v = make_float4(0.f, 0.f, 0.f, 0.f);
            if (bm + row < NNODES)
                v = *(const float4*)(x + (size_t)(bm + row) * NF + kq);
            *(__half2*)&As[row][kq]     = __floats2half2_rn(v.x, v.y);
            *(__half2*)&As[row][kq + 2] = __floats2half2_rn(v.z, v.w);
        }
    } else {
#pragma unroll
        for (int i = 0; i < 4; i++) {
            int e = tid + i * 256;
            int row = e >> 4;            // 16 uint4 per row
            int kq = (e & 15) * 8;
            uint4 v = make_uint4(0u, 0u, 0u, 0u);
            if (bm + row < NNODES)
                v = *(const uint4*)(g_h + (size_t)(bm + row) * NF + kq);
            *(uint32_t*)&As[row][kq]     = v.x;
            *(uint32_t*)&As[row][kq + 2] = v.y;
            *(uint32_t*)&As[row][kq + 4] = v.z;
            *(uint32_t*)&As[row][kq + 6] = v.w;
        }
    }
    // ---- stage full W tile natural layout: Wk[k][n] ----
#pragma unroll
    for (int i = 0; i < 32; i++) {
        int e = tid + i * 256;
        int kr = e >> 6;                 // 0..127
        int n2 = (e & 63) * 2;           // 0..126
        float2 v = *(const float2*)(B + (size_t)kr * NF + n2);
        *(__half2*)&Wk[kr][n2] = __floats2half2_rn(v.x, v.y);
    }
    __syncthreads();

    float acc[8][4];
#pragma unroll
    for (int tj = 0; tj < 8; tj++)
#pragma unroll
        for (int q = 0; q < 4; q++) acc[tj][q] = 0.0f;

    // per-lane ldmatrix sub-offsets
    int a_roff = (lm & 1) * 8 + lr;      // A: row offset within 16-row tile
    int a_koff = (lm >> 1) * 8;          // A: k offset within 16-k slice
    int b_koff = (lm & 1) * 8 + lr;      // B: k row within 16-k slice
    int b_noff = (lm >> 1) * 8;          // B: n offset within 16-n pair

#pragma unroll
    for (int kk = 0; kk < NF; kk += 16) {
        uint32_t a[4];
        ldsm_x4(a[0], a[1], a[2], a[3],
                smem_u32(&As[wr * 16 + a_roff][kk + a_koff]));
        uint32_t bf[4][4];
#pragma unroll
        for (int tjp = 0; tjp < 4; tjp++)
            ldsm_x4_t(bf[tjp][0], bf[tjp][1], bf[tjp][2], bf[tjp][3],
                      smem_u32(&Wk[kk + b_koff][wc * 64 + tjp * 16 + b_noff]));
#pragma unroll
        for (int tj = 0; tj < 8; tj++) {
            uint32_t b0 = bf[tj >> 1][(tj & 1) * 2 + 0];
            uint32_t b1 = bf[tj >> 1][(tj & 1) * 2 + 1];
            mma_f16(acc[tj], a, b0, b1);
        }
    }

#pragma unroll
    for (int tj = 0; tj < 8; tj++) {
        int row = bm + wr * 16 + g;
        int col = wc * 64 + tj * 8 + tig * 2;
        if (row < NNODES)
            *(__half2*)(g_hw + (size_t)row * NF + col) =
                __floats2half2_rn(acc[tj][0], acc[tj][1]);
        if (row + 8 < NNODES)
            *(__half2*)(g_hw + (size_t)(row + 8) * NF + col) =
                __floats2half2_rn(acc[tj][2], acc[tj][3]);
    }
}

// ------- gather (4-wide edge metadata) + self-loop + bias + relu -----------
template <bool DO_POOL>
__global__ __launch_bounds__(256) void k_gather(const float* __restrict__ ball,
                                                int layer,
                                                const int* __restrict__ batch) {
    int node = blockIdx.x * 8 + (threadIdx.x >> 5);
    if (node >= NNODES) return;
    int lane = threadIdx.x & 31;

    const __half* __restrict__ hw = g_hw;
    const float* __restrict__ bias = ball + layer * NF;

    float4 acc = make_float4(0.f, 0.f, 0.f, 0.f);
    int s = g_off[node];
    int e = g_off[node + 1];   // s, e multiples of 4; padding has enorm==0
    for (int p = s; p < e; p += 4) {
        int4 rr = *(const int4*)(g_row + p);
        float4 nm = *(const float4*)(g_enorm + p);
        uint2 w0 = *(const uint2*)(hw + (size_t)rr.x * NF + lane * 4);
        uint2 w1 = *(const uint2*)(hw + (size_t)rr.y * NF + lane * 4);
        uint2 w2 = *(const uint2*)(hw + (size_t)rr.z * NF + lane * 4);
        uint2 w3 = *(const uint2*)(hw + (size_t)rr.w * NF + lane * 4);
        float2 a0 = __half22float2(*(__half2*)&w0.x), a1 = __half22float2(*(__half2*)&w0.y);
        float2 b0 = __half22float2(*(__half2*)&w1.x), b1 = __half22float2(*(__half2*)&w1.y);
        float2 c0 = __half22float2(*(__half2*)&w2.x), c1 = __half22float2(*(__half2*)&w2.y);
        float2 d0 = __half22float2(*(__half2*)&w3.x), d1 = __half22float2(*(__half2*)&w3.y);
        acc.x += a0.x * nm.x + b0.x * nm.y + c0.x * nm.z + d0.x * nm.w;
        acc.y += a0.y * nm.x + b0.y * nm.y + c0.y * nm.z + d0.y * nm.w;
        acc.z += a1.x * nm.x + b1.x * nm.y + c1.x * nm.z + d1.x * nm.w;
        acc.w += a1.y * nm.x + b1.y * nm.y + c1.y * nm.z + d1.y * nm.w;
    }
    // self-loop
    {
        float di = g_dinv[node];
        float nm = di * di;
        uint2 w0 = *(const uint2*)(hw + (size_t)node * NF + lane * 4);
        float2 a0 = __half22float2(*(__half2*)&w0.x), a1 = __half22float2(*(__half2*)&w0.y);
        acc.x += a0.x * nm;
        acc.y += a0.y * nm;
        acc.z += a1.x * nm;
        acc.w += a1.y * nm;
    }
    float4 bb = *(const float4*)(bias + lane * 4);
    acc.x = fmaxf(acc.x + bb.x, 0.f);
    acc.y = fmaxf(acc.y + bb.y, 0.f);
    acc.z = fmaxf(acc.z + bb.z, 0.f);
    acc.w = fmaxf(acc.w + bb.w, 0.f);

    if (DO_POOL) {
        int gph = batch[node];
        gph = min(max(gph, 0), NGRAPH - 1);
        float* dst = g_pool + (size_t)gph * NF + lane * 4;
        atomicAdd(dst + 0, acc.x);
        atomicAdd(dst + 1, acc.y);
        atomicAdd(dst + 2, acc.z);
        atomicAdd(dst + 3, acc.w);
    } else {
        __half2 h01 = __floats2half2_rn(acc.x, acc.y);
        __half2 h23 = __floats2half2_rn(acc.z, acc.w);
        uint2 packed = make_uint2(*(uint32_t*)&h01, *(uint32_t*)&h23);
        *(uint2*)(g_h + (size_t)node * NF + lane * 4) = packed;
    }
}

// ---------------- output head ------------------
__global__ __launch_bounds__(128) void k_out(const float* __restrict__ Wout,
                                             const float* __restrict__ bout,
                                             float* __restrict__ out) {
    int w = blockIdx.x * 4 + (threadIdx.x >> 5);
    if (w >= NGRAPH) return;
    int lane = threadIdx.x & 31;
    float4 p = *(const float4*)(g_pool + (size_t)w * NF + lane * 4);
#pragma unroll
    for (int c = 0; c < NCLS; c++) {
        float sum = p.x * Wout[(lane * 4 + 0) * NCLS + c]
                  + p.y * Wout[(lane * 4 + 1) * NCLS + c]
                  + p.z * Wout[(lane * 4 + 2) * NCLS + c]
                  + p.w * Wout[(lane * 4 + 3) * NCLS + c];
#pragma unroll
        for (int o = 16; o > 0; o >>= 1)
            sum += __shfl_down_sync(0xffffffffu, sum, o);
        if (lane == 0) out[w * NCLS + c] = sum + bout[c];
    }
}

// ---------------- launch ----------
extern "C" void kernel_launch(void* const* d_in, const int* in_sizes, int n_in,
                              void* d_out, int out_size) {
    const float* x     = nullptr;
    const int*   ei    = nullptr;
    const int*   batch = nullptr;
    const float* W     = nullptr;
    const float* b     = nullptr;
    const float* Wout  = nullptr;
    const float* bout  = nullptr;
    for (int i = 0; i < n_in; i++) {
        switch (in_sizes[i]) {
            case NNODES * NF:      x     = (const float*)d_in[i]; break;
            case 2 * NEDGES:       ei    = (const int*)d_in[i];   break;
            case NNODES:           batch = (const int*)d_in[i];   break;
            case 3 * NF * NF:      W     = (const float*)d_in[i]; break;
            case 3 * NF:           b     = (const float*)d_in[i]; break;
            case NF * NCLS:        Wout  = (const float*)d_in[i]; break;
            case NCLS:             bout  = (const float*)d_in[i]; break;
            default: break;
        }
    }
    float* out = (float*)d_out;

    const int* rowp = ei;           // source nodes j
    const int* colp = ei + NEDGES;  // target nodes i

    cudaFuncSetAttribute(k_gemm, cudaFuncAttributeMaxDynamicSharedMemorySize,
                         GEMM_SMEM);

    k_zero<<<(NGRAPH * NF + 255) / 256, 256>>>();
    k_count<<<(NEDGES + 255) / 256, 256>>>(colp);
    k_scan_a<<<SCAN_BLOCKS, 1024>>>();
    // layer-0 GEMM depends only on x,W — launch #3 = profiler capture slot.
    k_gemm<<<(NNODES + BM - 1) / BM, 256, GEMM_SMEM>>>(x, W, 0);
    k_scan_b<<<1, 64>>>();
    k_scan_c<<<SCAN_BLOCKS, 1024>>>();
    k_fill<<<(NEDGES + 255) / 256, 256>>>(rowp, colp);

    k_gather<false><<<(NNODES + 7) / 8, 256>>>(b, 0, batch);
    k_gemm<<<(NNODES + BM - 1) / BM, 256, GEMM_SMEM>>>(x, W, 1);
    k_gather<false><<<(NNODES + 7) / 8, 256>>>(b, 1, batch);
    k_gemm<<<(NNODES + BM - 1) / BM, 256, GEMM_SMEM>>>(x, W, 2);
    k_gather<true><<<(NNODES + 7) / 8, 256>>>(b, 2, batch);

    k_out<<<NGRAPH / 4, 128>>>(Wout, bout, out);
}

// round 14
// speedup vs baseline: 1.1499x; 1.0490x over previous
#include <cuda_runtime.h>
#include <cuda_fp16.h>
#include <cstdint>

#define NNODES 50000
#define NEDGES 800000
#define NEPAD (NEDGES + 4 * NNODES)   // CSR capacity with per-node pad-to-4
#define NF 128
#define NGRAPH 512
#define NCLS 10
#define SCAN_BLOCKS ((NNODES + 1023) / 1024)   // 49

#define ASTRIDE 136                        // halves per smem row (272 B, 16B-aligned)
#define GEMM_SMEM (2 * 128 * ASTRIDE * 2)  // 69632 B

// ---------------- device scratch (static: no allocations allowed) ----------
__device__ __half g_h[NNODES * NF];     // layer activations (fp16)
__device__ __half g_hw[NNODES * NF];    // h @ W[l]  (fp16)
__device__ __half g_wh[3 * NF * NF];    // fp16 weights (pre-converted)
__device__ float  g_dinv[NNODES];
__device__ int    g_deg[NNODES];
__device__ int    g_off[NNODES + 1];    // padded CSR offsets (multiples of 4)
__device__ int    g_cur[NNODES];
__device__ __align__(16) int   g_row[NEPAD];    // zero-init: padding rows stay 0
__device__ __align__(16) float g_enorm[NEPAD];  // zero-init: padding norms stay 0
__device__ float  g_pool[NGRAPH * NF];
__device__ int    g_bsum[SCAN_BLOCKS];

// ---------------- init (+ W fp16 conversion, folded in) ----------
__global__ void k_zero(const float* __restrict__ W) {
    int i = blockIdx.x * blockDim.x + threadIdx.x;
    if (i < NGRAPH * NF) g_pool[i] = 0.0f;
    if (i < NNODES) g_deg[i] = 0;
    if (i < 3 * NF * NF / 4) {
        float4 v = *(const float4*)(W + (size_t)i * 4);
        __half2 h0 = __floats2half2_rn(v.x, v.y);
        __half2 h1 = __floats2half2_rn(v.z, v.w);
        *(uint2*)(g_wh + (size_t)i * 4) =
            make_uint2(*(uint32_t*)&h0, *(uint32_t*)&h1);
    }
}

__global__ void k_count(const int* __restrict__ col) {
    int e = blockIdx.x * blockDim.x + threadIdx.x;
    if (e < NEDGES) {
        int c = col[e];
        c = min(max(c, 0), NNODES - 1);
        atomicAdd(&g_deg[c], 1);
    }
}

// ---------- scan stage A over padded degrees (+ dinv fused) ----------
__global__ __launch_bounds__(1024) void k_scan_a() {
    int i = blockIdx.x * 1024 + threadIdx.x;
    int lane = threadIdx.x & 31;
    int wid = threadIdx.x >> 5;
    int deg = (i < NNODES) ? g_deg[i] : 0;
    if (i < NNODES) g_dinv[i] = rsqrtf((float)(deg + 1));  // +1 self-loop
    int v = (deg + 3) & ~3;   // pad each node's segment to multiple of 4

    int incl = v;
#pragma unroll
    for (int d = 1; d < 32; d <<= 1) {
        int t = __shfl_up_sync(0xffffffffu, incl, d);
        if (lane >= d) incl += t;
    }
    __shared__ int wsum[32];
    if (lane == 31) wsum[wid] = incl;
    __syncthreads();
    if (wid == 0) {
        int s = wsum[lane];
#pragma unroll
        for (int d = 1; d < 32; d <<= 1) {
            int t = __shfl_up_sync(0xffffffffu, s, d);
            if (lane >= d) s += t;
        }
        wsum[lane] = s;
    }
    __syncthreads();
    int warpoff = (wid > 0) ? wsum[wid - 1] : 0;
    int excl = warpoff + incl - v;
    if (i < NNODES) g_off[i] = excl;   // block-local exclusive
    if (threadIdx.x == 1023) g_bsum[blockIdx.x] = warpoff + incl;
}

// ---------- scan stage C: inline block-offset reduction + materialize ------
__global__ __launch_bounds__(1024) void k_scan_c() {
    __shared__ int sb[64];     // masked (j < bid)
    __shared__ int st[64];     // unmasked (for total)
    int tid = threadIdx.x;
    if (tid < 64) {
        int bv = (tid < SCAN_BLOCKS) ? g_bsum[tid] : 0;
        sb[tid] = (tid < blockIdx.x) ? bv : 0;
        st[tid] = bv;
    }
    __syncthreads();
    __shared__ int boff_s;
    if (tid == 0) {
        int s = 0;
#pragma unroll
        for (int j = 0; j < 64; j++) s += sb[j];
        boff_s = s;
        if (blockIdx.x == SCAN_BLOCKS - 1) {
            int tot = 0;
#pragma unroll
            for (int j = 0; j < 64; j++) tot += st[j];
            g_off[NNODES] = tot;   // padded total
        }
    }
    __syncthreads();
    int i = blockIdx.x * 1024 + tid;
    if (i < NNODES) {
        int o = g_off[i] + boff_s;
        g_off[i] = o;
        g_cur[i] = o;
    }
}

__global__ void k_fill(const int* __restrict__ rowp,
                       const int* __restrict__ colp) {
    int e = blockIdx.x * blockDim.x + threadIdx.x;
    if (e < NEDGES) {
        int c = colp[e];
        c = min(max(c, 0), NNODES - 1);
        int r = rowp[e];
        r = min(max(r, 0), NNODES - 1);
        int p = atomicAdd(&g_cur[c], 1);
        if (p >= 0 && p < NEPAD) {
            g_row[p] = r;
            g_enorm[p] = g_dinv[r] * g_dinv[c];
        }
    }
}

// ---------------- mma / ldmatrix helpers ----------------
__device__ __forceinline__ void mma_f16(float* c, const uint32_t* a,
                                        uint32_t b0, uint32_t b1) {
    asm volatile(
        "mma.sync.aligned.m16n8k16.row.col.f32.f16.f16.f32 "
        "{%0,%1,%2,%3}, {%4,%5,%6,%7}, {%8,%9}, {%0,%1,%2,%3};"
        : "+f"(c[0]), "+f"(c[1]), "+f"(c[2]), "+f"(c[3])
        : "r"(a[0]), "r"(a[1]), "r"(a[2]), "r"(a[3]), "r"(b0), "r"(b1));
}
__device__ __forceinline__ uint32_t smem_u32(const void* p) {
    return (uint32_t)__cvta_generic_to_shared(p);
}
__device__ __forceinline__ void ldsm_x4(uint32_t& r0, uint32_t& r1,
                                        uint32_t& r2, uint32_t& r3, uint32_t a) {
    asm volatile("ldmatrix.sync.aligned.m8n8.x4.shared.b16 {%0,%1,%2,%3}, [%4];"
                 : "=r"(r0), "=r"(r1), "=r"(r2), "=r"(r3) : "r"(a));
}
__device__ __forceinline__ void ldsm_x4_t(uint32_t& r0, uint32_t& r1,
                                          uint32_t& r2, uint32_t& r3, uint32_t a) {
    asm volatile("ldmatrix.sync.aligned.m8n8.x4.trans.shared.b16 {%0,%1,%2,%3}, [%4];"
                 : "=r"(r0), "=r"(r1), "=r"(r2), "=r"(r3) : "r"(a));
}

// -------- GEMM (fp16 m16n8k16, full-K 128x128 tiles, ldmatrix) -------------
// A = x (fp32, layer 0) or g_h (fp16). W = g_wh (fp16, pre-converted).
__global__ __launch_bounds__(256, 2) void k_gemm(const float* __restrict__ x,
                                                 int layer) {
    extern __shared__ __half sm[];
    __half (*As)[ASTRIDE] = (__half(*)[ASTRIDE])sm;                   // [m][k]
    __half (*Wk)[ASTRIDE] = (__half(*)[ASTRIDE])(sm + 128 * ASTRIDE); // [k][n]

    const __half* __restrict__ Bh = g_wh + (size_t)layer * NF * NF;

    int bm = blockIdx.x * 128;
    int tid = threadIdx.x;
    int warp = tid >> 5, lane = tid & 31;
    int wr = warp >> 1;        // m slab (32 rows)
    int wc = warp & 1;         // n slab (64 cols)
    int g = lane >> 2;
    int tig = lane & 3;
    int lm = lane >> 3;        // ldmatrix matrix id 0..3
    int lr = lane & 7;         // ldmatrix row-in-matrix

    // ---- stage full A tile (128 x 128 halves), one shot ----
    if (layer == 0) {
#pragma unroll
        for (int i = 0; i < 16; i++) {
            int e = tid + i * 256;
            int row = e >> 5;            // 32 float4 per row
            int kq = (e & 31) * 4;
            float4 v = make_float4(0.f, 0.f, 0.f, 0.f);
            if (bm + row < NNODES)
                v = *(const float4*)(x + (size_t)(bm + row) * NF + kq);
            *(__half2*)&As[row][kq]     = __floats2half2_rn(v.x, v.y);
            *(__half2*)&As[row][kq + 2] = __floats2half2_rn(v.z, v.w);
        }
    } else {
#pragma unroll
        for (int i = 0; i < 8; i++) {
            int e = tid + i * 256;
            int row = e >> 4;            // 16 uint4 per row
            int kq = (e & 15) * 8;
            uint4 v = make_uint4(0u, 0u, 0u, 0u);
            if (bm + row < NNODES)
                v = *(const uint4*)(g_h + (size_t)(bm + row) * NF + kq);
            *(uint32_t*)&As[row][kq]     = v.x;
            *(uint32_t*)&As[row][kq + 2] = v.y;
            *(uint32_t*)&As[row][kq + 4] = v.z;
            *(uint32_t*)&As[row][kq + 6] = v.w;
        }
    }
    // ---- stage full W tile (fp16 source, natural [k][n] layout) ----
#pragma unroll
    for (int i = 0; i < 8; i++) {
        int e = tid + i * 256;
        int kr = e >> 4;                 // 0..127
        int nq = (e & 15) * 8;           // 0..120
        uint4 v = *(const uint4*)(Bh + (size_t)kr * NF + nq);
        *(uint32_t*)&Wk[kr][nq]     = v.x;
        *(uint32_t*)&Wk[kr][nq + 2] = v.y;
        *(uint32_t*)&Wk[kr][nq + 4] = v.z;
        *(uint32_t*)&Wk[kr][nq + 6] = v.w;
    }
    __syncthreads();

    float acc[2][8][4];
#pragma unroll
    for (int ti = 0; ti < 2; ti++)
#pragma unroll
        for (int tj = 0; tj < 8; tj++)
#pragma unroll
            for (int q = 0; q < 4; q++) acc[ti][tj][q] = 0.0f;

    // per-lane ldmatrix sub-offsets
    int a_roff = (lm & 1) * 8 + lr;      // A: row offset within 16-row tile
    int a_koff = (lm >> 1) * 8;          // A: k offset within 16-k slice
    int b_koff = (lm & 1) * 8 + lr;      // B: k row within 16-k slice
    int b_noff = (lm >> 1) * 8;          // B: n offset within 16-n pair

#pragma unroll
    for (int kk = 0; kk < NF; kk += 16) {
        uint32_t a[2][4];
        ldsm_x4(a[0][0], a[0][1], a[0][2], a[0][3],
                smem_u32(&As[wr * 32 + a_roff][kk + a_koff]));
        ldsm_x4(a[1][0], a[1][1], a[1][2], a[1][3],
                smem_u32(&As[wr * 32 + 16 + a_roff][kk + a_koff]));
        uint32_t bf[4][4];
#pragma unroll
        for (int tjp = 0; tjp < 4; tjp++)
            ldsm_x4_t(bf[tjp][0], bf[tjp][1], bf[tjp][2], bf[tjp][3],
                      smem_u32(&Wk[kk + b_koff][wc * 64 + tjp * 16 + b_noff]));
#pragma unroll
        for (int tj = 0; tj < 8; tj++) {
            uint32_t b0 = bf[tj >> 1][(tj & 1) * 2 + 0];
            uint32_t b1 = bf[tj >> 1][(tj & 1) * 2 + 1];
            mma_f16(acc[0][tj], a[0], b0, b1);
            mma_f16(acc[1][tj], a[1], b0, b1);
        }
    }

#pragma unroll
    for (int ti = 0; ti < 2; ti++) {
#pragma unroll
        for (int tj = 0; tj < 8; tj++) {
            int row = bm + wr * 32 + ti * 16 + g;
            int col = wc * 64 + tj * 8 + tig * 2;
            if (row < NNODES)
                *(__half2*)(g_hw + (size_t)row * NF + col) =
                    __floats2half2_rn(acc[ti][tj][0], acc[ti][tj][1]);
            if (row + 8 < NNODES)
                *(__half2*)(g_hw + (size_t)(row + 8) * NF + col) =
                    __floats2half2_rn(acc[ti][tj][2], acc[ti][tj][3]);
        }
    }
}

// ------- gather (4-wide edge metadata) + self-loop + bias + relu -----------
template <bool DO_POOL>
__global__ __launch_bounds__(256) void k_gather(const float* __restrict__ ball,
                                                int layer,
                                                const int* __restrict__ batch) {
    int node = blockIdx.x * 8 + (threadIdx.x >> 5);
    if (node >= NNODES) return;
    int lane = threadIdx.x & 31;

    const __half* __restrict__ hw = g_hw;
    const float* __restrict__ bias = ball + layer * NF;

    float4 acc = make_float4(0.f, 0.f, 0.f, 0.f);
    int s = g_off[node];
    int e = g_off[node + 1];   // s, e multiples of 4; padding has enorm==0
    for (int p = s; p < e; p += 4) {
        int4 rr = *(const int4*)(g_row + p);
        float4 nm = *(const float4*)(g_enorm + p);
        uint2 w0 = *(const uint2*)(hw + (size_t)rr.x * NF + lane * 4);
        uint2 w1 = *(const uint2*)(hw + (size_t)rr.y * NF + lane * 4);
        uint2 w2 = *(const uint2*)(hw + (size_t)rr.z * NF + lane * 4);
        uint2 w3 = *(const uint2*)(hw + (size_t)rr.w * NF + lane * 4);
        float2 a0 = __half22float2(*(__half2*)&w0.x), a1 = __half22float2(*(__half2*)&w0.y);
        float2 b0 = __half22float2(*(__half2*)&w1.x), b1 = __half22float2(*(__half2*)&w1.y);
        float2 c0 = __half22float2(*(__half2*)&w2.x), c1 = __half22float2(*(__half2*)&w2.y);
        float2 d0 = __half22float2(*(__half2*)&w3.x), d1 = __half22float2(*(__half2*)&w3.y);
        acc.x += a0.x * nm.x + b0.x * nm.y + c0.x * nm.z + d0.x * nm.w;
        acc.y += a0.y * nm.x + b0.y * nm.y + c0.y * nm.z + d0.y * nm.w;
        acc.z += a1.x * nm.x + b1.x * nm.y + c1.x * nm.z + d1.x * nm.w;
        acc.w += a1.y * nm.x + b1.y * nm.y + c1.y * nm.z + d1.y * nm.w;
    }
    // self-loop
    {
        float di = g_dinv[node];
        float nm = di * di;
        uint2 w0 = *(const uint2*)(hw + (size_t)node * NF + lane * 4);
        float2 a0 = __half22float2(*(__half2*)&w0.x), a1 = __half22float2(*(__half2*)&w0.y);
        acc.x += a0.x * nm;
        acc.y += a0.y * nm;
        acc.z += a1.x * nm;
        acc.w += a1.y * nm;
    }
    float4 bb = *(const float4*)(bias + lane * 4);
    acc.x = fmaxf(acc.x + bb.x, 0.f);
    acc.y = fmaxf(acc.y + bb.y, 0.f);
    acc.z = fmaxf(acc.z + bb.z, 0.f);
    acc.w = fmaxf(acc.w + bb.w, 0.f);

    if (DO_POOL) {
        int gph = batch[node];
        gph = min(max(gph, 0), NGRAPH - 1);
        float* dst = g_pool + (size_t)gph * NF + lane * 4;
        atomicAdd(dst + 0, acc.x);
        atomicAdd(dst + 1, acc.y);
        atomicAdd(dst + 2, acc.z);
        atomicAdd(dst + 3, acc.w);
    } else {
        __half2 h01 = __floats2half2_rn(acc.x, acc.y);
        __half2 h23 = __floats2half2_rn(acc.z, acc.w);
        uint2 packed = make_uint2(*(uint32_t*)&h01, *(uint32_t*)&h23);
        *(uint2*)(g_h + (size_t)node * NF + lane * 4) = packed;
    }
}

// ---------------- output head ------------------
__global__ __launch_bounds__(128) void k_out(const float* __restrict__ Wout,
                                             const float* __restrict__ bout,
                                             float* __restrict__ out) {
    int w = blockIdx.x * 4 + (threadIdx.x >> 5);
    if (w >= NGRAPH) return;
    int lane = threadIdx.x & 31;
    float4 p = *(const float4*)(g_pool + (size_t)w * NF + lane * 4);
#pragma unroll
    for (int c = 0; c < NCLS; c++) {
        float sum = p.x * Wout[(lane * 4 + 0) * NCLS + c]
                  + p.y * Wout[(lane * 4 + 1) * NCLS + c]
                  + p.z * Wout[(lane * 4 + 2) * NCLS + c]
                  + p.w * Wout[(lane * 4 + 3) * NCLS + c];
#pragma unroll
        for (int o = 16; o > 0; o >>= 1)
            sum += __shfl_down_sync(0xffffffffu, sum, o);
        if (lane == 0) out[w * NCLS + c] = sum + bout[c];
    }
}

// ---------------- launch ----------
extern "C" void kernel_launch(void* const* d_in, const int* in_sizes, int n_in,
                              void* d_out, int out_size) {
    const float* x     = nullptr;
    const int*   ei    = nullptr;
    const int*   batch = nullptr;
    const float* W     = nullptr;
    const float* b     = nullptr;
    const float* Wout  = nullptr;
    const float* bout  = nullptr;
    for (int i = 0; i < n_in; i++) {
        switch (in_sizes[i]) {
            case NNODES * NF:      x     = (const float*)d_in[i]; break;
            case 2 * NEDGES:       ei    = (const int*)d_in[i];   break;
            case NNODES:           batch = (const int*)d_in[i];   break;
            case 3 * NF * NF:      W     = (const float*)d_in[i]; break;
            case 3 * NF:           b     = (const float*)d_in[i]; break;
            case NF * NCLS:        Wout  = (const float*)d_in[i]; break;
            case NCLS:             bout  = (const float*)d_in[i]; break;
            default: break;
        }
    }
    float* out = (float*)d_out;

    const int* rowp = ei;           // source nodes j
    const int* colp = ei + NEDGES;  // target nodes i

    cudaFuncSetAttribute(k_gemm, cudaFuncAttributeMaxDynamicSharedMemorySize,
                         GEMM_SMEM);

    k_zero<<<(NGRAPH * NF + 255) / 256, 256>>>(W);
    k_count<<<(NEDGES + 255) / 256, 256>>>(colp);
    k_scan_a<<<SCAN_BLOCKS, 1024>>>();
    // layer-0 GEMM depends only on x, g_wh — launch #4 = profiler capture slot.
    k_gemm<<<(NNODES + 127) / 128, 256, GEMM_SMEM>>>(x, 0);
    k_scan_c<<<SCAN_BLOCKS, 1024>>>();
    k_fill<<<(NEDGES + 255) / 256, 256>>>(rowp, colp);

    k_gather<false><<<(NNODES + 7) / 8, 256>>>(b, 0, batch);
    k_gemm<<<(NNODES + 127) / 128, 256, GEMM_SMEM>>>(x, 1);
    k_gather<false><<<(NNODES + 7) / 8, 256>>>(b, 1, batch);
    k_gemm<<<(NNODES + 127) / 128, 256, GEMM_SMEM>>>(x, 2);
    k_gather<true><<<(NNODES + 7) / 8, 256>>>(b, 2, batch);

    k_out<<<NGRAPH / 4, 128>>>(Wout, bout, out);
}

// round 15
// speedup vs baseline: 1.3055x; 1.1353x over previous
#include <cuda_runtime.h>
#include <cuda_fp16.h>
#include <cstdint>

#define NNODES 50000
#define NEDGES 800000
#define NEPAD (NEDGES + 4 * NNODES)   // CSR capacity with per-node pad-to-4
#define NF 128
#define NGRAPH 512
#define NCLS 10
#define SCAN_BLOCKS ((NNODES + 1023) / 1024)   // 49

#define ASTRIDE 136                        // halves per smem row (272 B, 16B-aligned)
#define GEMM_SMEM (2 * 128 * ASTRIDE * 2)  // 69632 B

// ---------------- device scratch (static: no allocations allowed) ----------
__device__ __half g_h[NNODES * NF];        // layer activations (fp16)
__device__ __half g_hw[(NNODES + 1) * NF]; // dinv-scaled h@W; row NNODES = zeros (sentinel, never written)
__device__ __half g_wh[3 * NF * NF];       // fp16 weights (pre-converted)
__device__ float  g_dinv[NNODES];
__device__ int    g_deg[NNODES];
__device__ int    g_off[NNODES + 1];       // padded CSR offsets (multiples of 4)
__device__ int    g_cur[NNODES];
__device__ __align__(16) int g_row[NEPAD]; // padding entries set to NNODES (sentinel)
__device__ float  g_pool[NGRAPH * NF];
__device__ int    g_bsum[SCAN_BLOCKS];

// ---------------- init (+ W fp16 conversion, folded in) ----------
__global__ void k_zero(const float* __restrict__ W) {
    int i = blockIdx.x * blockDim.x + threadIdx.x;
    if (i < NGRAPH * NF) g_pool[i] = 0.0f;
    if (i < NNODES) g_deg[i] = 0;
    if (i < 3 * NF * NF / 4) {
        float4 v = *(const float4*)(W + (size_t)i * 4);
        __half2 h0 = __floats2half2_rn(v.x, v.y);
        __half2 h1 = __floats2half2_rn(v.z, v.w);
        *(uint2*)(g_wh + (size_t)i * 4) =
            make_uint2(*(uint32_t*)&h0, *(uint32_t*)&h1);
    }
}

__global__ void k_count(const int* __restrict__ col) {
    int e = blockIdx.x * blockDim.x + threadIdx.x;
    if (e < NEDGES) {
        int c = col[e];
        c = min(max(c, 0), NNODES - 1);
        atomicAdd(&g_deg[c], 1);
    }
}

// ---------- scan stage A over padded degrees (+ dinv fused) ----------
__global__ __launch_bounds__(1024) void k_scan_a() {
    int i = blockIdx.x * 1024 + threadIdx.x;
    int lane = threadIdx.x & 31;
    int wid = threadIdx.x >> 5;
    int deg = (i < NNODES) ? g_deg[i] : 0;
    if (i < NNODES) g_dinv[i] = rsqrtf((float)(deg + 1));  // +1 self-loop
    int v = (deg + 3) & ~3;   // pad each node's segment to multiple of 4

    int incl = v;
#pragma unroll
    for (int d = 1; d < 32; d <<= 1) {
        int t = __shfl_up_sync(0xffffffffu, incl, d);
        if (lane >= d) incl += t;
    }
    __shared__ int wsum[32];
    if (lane == 31) wsum[wid] = incl;
    __syncthreads();
    if (wid == 0) {
        int s = wsum[lane];
#pragma unroll
        for (int d = 1; d < 32; d <<= 1) {
            int t = __shfl_up_sync(0xffffffffu, s, d);
            if (lane >= d) s += t;
        }
        wsum[lane] = s;
    }
    __syncthreads();
    int warpoff = (wid > 0) ? wsum[wid - 1] : 0;
    int excl = warpoff + incl - v;
    if (i < NNODES) g_off[i] = excl;   // block-local exclusive
    if (threadIdx.x == 1023) g_bsum[blockIdx.x] = warpoff + incl;
}

// ---------- scan stage C: block offsets + cursors + pad sentinels ----------
__global__ __launch_bounds__(1024) void k_scan_c() {
    __shared__ int sb[64];
    __shared__ int st[64];
    int tid = threadIdx.x;
    if (tid < 64) {
        int bv = (tid < SCAN_BLOCKS) ? g_bsum[tid] : 0;
        sb[tid] = (tid < blockIdx.x) ? bv : 0;
        st[tid] = bv;
    }
    __syncthreads();
    __shared__ int boff_s;
    if (tid == 0) {
        int s = 0;
#pragma unroll
        for (int j = 0; j < 64; j++) s += sb[j];
        boff_s = s;
        if (blockIdx.x == SCAN_BLOCKS - 1) {
            int tot = 0;
#pragma unroll
            for (int j = 0; j < 64; j++) tot += st[j];
            g_off[NNODES] = tot;
        }
    }
    __syncthreads();
    int i = blockIdx.x * 1024 + tid;
    if (i < NNODES) {
        int o = g_off[i] + boff_s;
        g_off[i] = o;
        g_cur[i] = o;
        int d = g_deg[i];
        int pd = (d + 3) & ~3;
        for (int q = o + d; q < o + pd; q++) g_row[q] = NNODES;  // sentinel -> zero row
    }
}

__global__ void k_fill(const int* __restrict__ rowp,
                       const int* __restrict__ colp) {
    int e = blockIdx.x * blockDim.x + threadIdx.x;
    if (e < NEDGES) {
        int c = colp[e];
        c = min(max(c, 0), NNODES - 1);
        int r = rowp[e];
        r = min(max(r, 0), NNODES - 1);
        int p = atomicAdd(&g_cur[c], 1);
        if (p >= 0 && p < NEPAD) g_row[p] = r;
    }
}

// ---------------- mma / ldmatrix helpers ----------------
__device__ __forceinline__ void mma_f16(float* c, const uint32_t* a,
                                        uint32_t b0, uint32_t b1) {
    asm volatile(
        "mma.sync.aligned.m16n8k16.row.col.f32.f16.f16.f32 "
        "{%0,%1,%2,%3}, {%4,%5,%6,%7}, {%8,%9}, {%0,%1,%2,%3};"
        : "+f"(c[0]), "+f"(c[1]), "+f"(c[2]), "+f"(c[3])
        : "r"(a[0]), "r"(a[1]), "r"(a[2]), "r"(a[3]), "r"(b0), "r"(b1));
}
__device__ __forceinline__ uint32_t smem_u32(const void* p) {
    return (uint32_t)__cvta_generic_to_shared(p);
}
__device__ __forceinline__ void ldsm_x4(uint32_t& r0, uint32_t& r1,
                                        uint32_t& r2, uint32_t& r3, uint32_t a) {
    asm volatile("ldmatrix.sync.aligned.m8n8.x4.shared.b16 {%0,%1,%2,%3}, [%4];"
                 : "=r"(r0), "=r"(r1), "=r"(r2), "=r"(r3) : "r"(a));
}
__device__ __forceinline__ void ldsm_x4_t(uint32_t& r0, uint32_t& r1,
                                          uint32_t& r2, uint32_t& r3, uint32_t a) {
    asm volatile("ldmatrix.sync.aligned.m8n8.x4.trans.shared.b16 {%0,%1,%2,%3}, [%4];"
                 : "=r"(r0), "=r"(r1), "=r"(r2), "=r"(r3) : "r"(a));
}

// -------- GEMM: g_hw = dinv-scaled (A @ W[l]) in fp16 ----------------------
// A = x (fp32, layer 0) or g_h (fp16). W = g_wh. Epilogue multiplies by dinv[row].
__global__ __launch_bounds__(256, 2) void k_gemm(const float* __restrict__ x,
                                                 int layer) {
    extern __shared__ __half sm[];
    __half (*As)[ASTRIDE] = (__half(*)[ASTRIDE])sm;                   // [m][k]
    __half (*Wk)[ASTRIDE] = (__half(*)[ASTRIDE])(sm + 128 * ASTRIDE); // [k][n]

    const __half* __restrict__ Bh = g_wh + (size_t)layer * NF * NF;

    int bm = blockIdx.x * 128;
    int tid = threadIdx.x;
    int warp = tid >> 5, lane = tid & 31;
    int wr = warp >> 1;
    int wc = warp & 1;
    int g = lane >> 2;
    int tig = lane & 3;
    int lm = lane >> 3;
    int lr = lane & 7;

    if (layer == 0) {
#pragma unroll
        for (int i = 0; i < 16; i++) {
            int e = tid + i * 256;
            int row = e >> 5;
            int kq = (e & 31) * 4;
            float4 v = make_float4(0.f, 0.f, 0.f, 0.f);
            if (bm + row < NNODES)
                v = *(const float4*)(x + (size_t)(bm + row) * NF + kq);
            *(__half2*)&As[row][kq]     = __floats2half2_rn(v.x, v.y);
            *(__half2*)&As[row][kq + 2] = __floats2half2_rn(v.z, v.w);
        }
    } else {
#pragma unroll
        for (int i = 0; i < 8; i++) {
            int e = tid + i * 256;
            int row = e >> 4;
            int kq = (e & 15) * 8;
            uint4 v = make_uint4(0u, 0u, 0u, 0u);
            if (bm + row < NNODES)
                v = *(const uint4*)(g_h + (size_t)(bm + row) * NF + kq);
            *(uint32_t*)&As[row][kq]     = v.x;
            *(uint32_t*)&As[row][kq + 2] = v.y;
            *(uint32_t*)&As[row][kq + 4] = v.z;
            *(uint32_t*)&As[row][kq + 6] = v.w;
        }
    }
#pragma unroll
    for (int i = 0; i < 8; i++) {
        int e = tid + i * 256;
        int kr = e >> 4;
        int nq = (e & 15) * 8;
        uint4 v = *(const uint4*)(Bh + (size_t)kr * NF + nq);
        *(uint32_t*)&Wk[kr][nq]     = v.x;
        *(uint32_t*)&Wk[kr][nq + 2] = v.y;
        *(uint32_t*)&Wk[kr][nq + 4] = v.z;
        *(uint32_t*)&Wk[kr][nq + 6] = v.w;
    }
    __syncthreads();

    float acc[2][8][4];
#pragma unroll
    for (int ti = 0; ti < 2; ti++)
#pragma unroll
        for (int tj = 0; tj < 8; tj++)
#pragma unroll
            for (int q = 0; q < 4; q++) acc[ti][tj][q] = 0.0f;

    int a_roff = (lm & 1) * 8 + lr;
    int a_koff = (lm >> 1) * 8;
    int b_koff = (lm & 1) * 8 + lr;
    int b_noff = (lm >> 1) * 8;

#pragma unroll
    for (int kk = 0; kk < NF; kk += 16) {
        uint32_t a[2][4];
        ldsm_x4(a[0][0], a[0][1], a[0][2], a[0][3],
                smem_u32(&As[wr * 32 + a_roff][kk + a_koff]));
        ldsm_x4(a[1][0], a[1][1], a[1][2], a[1][3],
                smem_u32(&As[wr * 32 + 16 + a_roff][kk + a_koff]));
        uint32_t bf[4][4];
#pragma unroll
        for (int tjp = 0; tjp < 4; tjp++)
            ldsm_x4_t(bf[tjp][0], bf[tjp][1], bf[tjp][2], bf[tjp][3],
                      smem_u32(&Wk[kk + b_koff][wc * 64 + tjp * 16 + b_noff]));
#pragma unroll
        for (int tj = 0; tj < 8; tj++) {
            uint32_t b0 = bf[tj >> 1][(tj & 1) * 2 + 0];
            uint32_t b1 = bf[tj >> 1][(tj & 1) * 2 + 1];
            mma_f16(acc[0][tj], a[0], b0, b1);
            mma_f16(acc[1][tj], a[1], b0, b1);
        }
    }

    // epilogue: scale by dinv[row], store fp16
#pragma unroll
    for (int ti = 0; ti < 2; ti++) {
        int row = bm + wr * 32 + ti * 16 + g;
        float dv0 = (row < NNODES) ? g_dinv[row] : 0.f;
        float dv8 = (row + 8 < NNODES) ? g_dinv[row + 8] : 0.f;
#pragma unroll
        for (int tj = 0; tj < 8; tj++) {
            int col = wc * 64 + tj * 8 + tig * 2;
            if (row < NNODES)
                *(__half2*)(g_hw + (size_t)row * NF + col) =
                    __floats2half2_rn(acc[ti][tj][0] * dv0, acc[ti][tj][1] * dv0);
            if (row + 8 < NNODES)
                *(__half2*)(g_hw + (size_t)(row + 8) * NF + col) =
                    __floats2half2_rn(acc[ti][tj][2] * dv8, acc[ti][tj][3] * dv8);
        }
    }
}

// ------- gather: fp16 sum of pre-scaled rows + self, then dinv*acc + b -----
template <bool DO_POOL>
__global__ __launch_bounds__(256) void k_gather(const float* __restrict__ ball,
                                                int layer,
                                                const int* __restrict__ batch) {
    int node = blockIdx.x * 8 + (threadIdx.x >> 5);
    if (node >= NNODES) return;
    int lane = threadIdx.x & 31;

    const __half* __restrict__ hw = g_hw;
    const float* __restrict__ bias = ball + layer * NF;

    __half2 a01 = __floats2half2_rn(0.f, 0.f);
    __half2 a23 = __floats2half2_rn(0.f, 0.f);
    int s = g_off[node];
    int e = g_off[node + 1];   // multiples of 4; padding rows -> zero sentinel
    for (int p = s; p < e; p += 4) {
        int4 rr = *(const int4*)(g_row + p);
        uint2 w0 = *(const uint2*)(hw + (size_t)rr.x * NF + lane * 4);
        uint2 w1 = *(const uint2*)(hw + (size_t)rr.y * NF + lane * 4);
        uint2 w2 = *(const uint2*)(hw + (size_t)rr.z * NF + lane * 4);
        uint2 w3 = *(const uint2*)(hw + (size_t)rr.w * NF + lane * 4);
        a01 = __hadd2(a01, *(__half2*)&w0.x); a23 = __hadd2(a23, *(__half2*)&w0.y);
        a01 = __hadd2(a01, *(__half2*)&w1.x); a23 = __hadd2(a23, *(__half2*)&w1.y);
        a01 = __hadd2(a01, *(__half2*)&w2.x); a23 = __hadd2(a23, *(__half2*)&w2.y);
        a01 = __hadd2(a01, *(__half2*)&w3.x); a23 = __hadd2(a23, *(__half2*)&w3.y);
    }
    // self-loop (hw is pre-scaled by dinv[node])
    {
        uint2 ws = *(const uint2*)(hw + (size_t)node * NF + lane * 4);
        a01 = __hadd2(a01, *(__half2*)&ws.x);
        a23 = __hadd2(a23, *(__half2*)&ws.y);
    }
    float di = g_dinv[node];
    float2 f01 = __half22float2(a01);
    float2 f23 = __half22float2(a23);
    float4 bb = *(const float4*)(bias + lane * 4);
    float4 r;
    r.x = fmaxf(fmaf(f01.x, di, bb.x), 0.f);
    r.y = fmaxf(fmaf(f01.y, di, bb.y), 0.f);
    r.z = fmaxf(fmaf(f23.x, di, bb.z), 0.f);
    r.w = fmaxf(fmaf(f23.y, di, bb.w), 0.f);

    if (DO_POOL) {
        int gph = batch[node];
        gph = min(max(gph, 0), NGRAPH - 1);
        float* dst = g_pool + (size_t)gph * NF + lane * 4;
        atomicAdd(dst + 0, r.x);
        atomicAdd(dst + 1, r.y);
        atomicAdd(dst + 2, r.z);
        atomicAdd(dst + 3, r.w);
    } else {
        __half2 h01 = __floats2half2_rn(r.x, r.y);
        __half2 h23 = __floats2half2_rn(r.z, r.w);
        *(uint2*)(g_h + (size_t)node * NF + lane * 4) =
            make_uint2(*(uint32_t*)&h01, *(uint32_t*)&h23);
    }
}

// ---------------- output head ------------------
__global__ __launch_bounds__(128) void k_out(const float* __restrict__ Wout,
                                             const float* __restrict__ bout,
                                             float* __restrict__ out) {
    int w = blockIdx.x * 4 + (threadIdx.x >> 5);
    if (w >= NGRAPH) return;
    int lane = threadIdx.x & 31;
    float4 p = *(const float4*)(g_pool + (size_t)w * NF + lane * 4);
#pragma unroll
    for (int c = 0; c < NCLS; c++) {
        float sum = p.x * Wout[(lane * 4 + 0) * NCLS + c]
                  + p.y * Wout[(lane * 4 + 1) * NCLS + c]
                  + p.z * Wout[(lane * 4 + 2) * NCLS + c]
                  + p.w * Wout[(lane * 4 + 3) * NCLS + c];
#pragma unroll
        for (int o = 16; o > 0; o >>= 1)
            sum += __shfl_down_sync(0xffffffffu, sum, o);
        if (lane == 0) out[w * NCLS + c] = sum + bout[c];
    }
}

// ---------------- launch ----------
extern "C" void kernel_launch(void* const* d_in, const int* in_sizes, int n_in,
                              void* d_out, int out_size) {
    const float* x     = nullptr;
    const int*   ei    = nullptr;
    const int*   batch = nullptr;
    const float* W     = nullptr;
    const float* b     = nullptr;
    const float* Wout  = nullptr;
    const float* bout  = nullptr;
    for (int i = 0; i < n_in; i++) {
        switch (in_sizes[i]) {
            case NNODES * NF:      x     = (const float*)d_in[i]; break;
            case 2 * NEDGES:       ei    = (const int*)d_in[i];   break;
            case NNODES:           batch = (const int*)d_in[i];   break;
            case 3 * NF * NF:      W     = (const float*)d_in[i]; break;
            case 3 * NF:           b     = (const float*)d_in[i]; break;
            case NF * NCLS:        Wout  = (const float*)d_in[i]; break;
            case NCLS:             bout  = (const float*)d_in[i]; break;
            default: break;
        }
    }
    float* out = (float*)d_out;

    const int* rowp = ei;           // source nodes j
    const int* colp = ei + NEDGES;  // target nodes i

    cudaFuncSetAttribute(k_gemm, cudaFuncAttributeMaxDynamicSharedMemorySize,
                         GEMM_SMEM);

    k_zero<<<(NGRAPH * NF + 255) / 256, 256>>>(W);
    k_count<<<(NEDGES + 255) / 256, 256>>>(colp);
    k_scan_a<<<SCAN_BLOCKS, 1024>>>();
    // layer-0 GEMM (needs x, g_wh, g_dinv from scan_a) — profiler capture slot.
    k_gemm<<<(NNODES + 127) / 128, 256, GEMM_SMEM>>>(x, 0);
    k_scan_c<<<SCAN_BLOCKS, 1024>>>();
    k_fill<<<(NEDGES + 255) / 256, 256>>>(rowp, colp);

    k_gather<false><<<(NNODES + 7) / 8, 256>>>(b, 0, batch);
    k_gemm<<<(NNODES + 127) / 128, 256, GEMM_SMEM>>>(x, 1);
    k_gather<false><<<(NNODES + 7) / 8, 256>>>(b, 1, batch);
    k_gemm<<<(NNODES + 127) / 128, 256, GEMM_SMEM>>>(x, 2);
    k_gather<true><<<(NNODES + 7) / 8, 256>>>(b, 2, batch);

    k_out<<<NGRAPH / 4, 128>>>(Wout, bout, out);
}